// round 9
// baseline (speedup 1.0000x reference)
#include <cuda_runtime.h>
#include <stdint.h>

#define BATCH   32768
#define NTREE   256
#define NNODE   2047
#define NFEAT   256
#define NCLS    8
#define DEPTH   10
#define SCHUNK  128
#define THREADS 512           // 128 samples x 4 tree-lanes (2 chains each)
#define GTREES  8
#define NCHUNK  (BATCH / SCHUNK)          // 256
#define NGROUPS (NTREE / GTREES)          // 32
#define NITEMS  (NCHUNK * NGROUPS)        // 8192, chunk-major
#define NSM     148
#define NSLOT   1024          // u32 slots per tree -> 4KB slab
#define GRPBYTES (GTREES * NSLOT * 4)     // 32768
#define SEG     2048          // padded thresholds per feature

// smem map: [0,64K) qx-tile u16 | [64K,128K) 2x32K node bufs | idx x2 | mbars
#define SM_X      0
#define SM_NODES  65536
#define SM_IDX    131072
#define IDX_PITCH 9
#define IDX_BYTES (SCHUNK * IDX_PITCH * 4)   // 4608
#define SM_MBAR   (SM_IDX + 2 * IDX_BYTES)   // 140288
#define SM_TOTAL  (SM_MBAR + 16)

__device__ int      g_cnt[NFEAT];
__device__ float    g_thr[NFEAT * SEG];        // per-feature sorted thresholds (+INF pad)
__device__ unsigned g_nodes4[NTREE * NSLOT];   // packed: feat<<24 | (rank+1)
__device__ float    g_xT[NFEAT * BATCH];       // fp32 transpose intermediate
__device__ uint16_t g_qxT[NFEAT * BATCH];      // quantized x, [feature][sample]

// ---------------- 1: zero counters, fill thr with +INF ----------------
__global__ void zero_k() {
    int i = blockIdx.x * blockDim.x + threadIdx.x;
    if (i < NFEAT * SEG) g_thr[i] = __int_as_float(0x7F800000);
    if (i < NFEAT) g_cnt[i] = 0;
}

// ---------------- 2: transpose x + scatter thresholds by feature ----------------
__global__ void prep1_k(const float* __restrict__ x,
                        const int* __restrict__ features,
                        const float* __restrict__ thresholds) {
    int b = blockIdx.x;
    const int TBLK = (NFEAT / 32) * (BATCH / 32);
    if (b < TBLK) {
        __shared__ float tile[32][33];
        int f0 = (b & 7) * 32, s0 = (b >> 3) * 32;
        int lx = threadIdx.x & 31, ly = threadIdx.x >> 5;   // 256 threads
        #pragma unroll
        for (int k = ly; k < 32; k += 8)
            tile[k][lx] = x[(size_t)(s0 + k) * NFEAT + f0 + lx];
        __syncthreads();
        #pragma unroll
        for (int k = ly; k < 32; k += 8)
            g_xT[(size_t)(f0 + k) * BATCH + s0 + lx] = tile[lx][k];
    } else {
        int i = (b - TBLK) * 256 + threadIdx.x;
        if (i < NTREE * 1023) {
            int t = i / 1023;
            int n = i - t * 1023;                 // internal node 0..1022
            int src = t * NNODE + n;
            int f = features[src];
            int pos = atomicAdd(&g_cnt[f], 1);
            g_thr[f * SEG + pos] = thresholds[src];
        }
    }
}

// ---------------- 3: bitonic sort each feature segment (ascending) ----------------
__global__ void sort_k() {
    __shared__ float s[SEG];
    float* seg = g_thr + blockIdx.x * SEG;
    for (int i = threadIdx.x; i < SEG; i += 512) s[i] = seg[i];
    __syncthreads();
    for (int k = 2; k <= SEG; k <<= 1)
        for (int j = k >> 1; j > 0; j >>= 1) {
            #pragma unroll
            for (int m = 0; m < SEG / 512 / 2 * 2; m++) {   // 4 sub-iters
                int i = threadIdx.x + 512 * m;
                int ixj = i ^ j;
                if (ixj > i) {
                    bool up = (i & k) == 0;
                    float a = s[i], c = s[ixj];
                    if ((a > c) == up) { s[i] = c; s[ixj] = a; }
                }
            }
            __syncthreads();
        }
    for (int i = threadIdx.x; i < SEG; i += 512) seg[i] = s[i];
}

// ---------------- 4: pack nodes: feat<<24 | (lower_bound+1) ----------------
__global__ void pack_k(const int* __restrict__ features,
                       const float* __restrict__ thresholds) {
    int i = blockIdx.x * blockDim.x + threadIdx.x;
    if (i >= NTREE * 1023) return;
    int t = i / 1023;
    int n = i - t * 1023;
    int src = t * NNODE + n;
    int f = features[src];
    float thr = thresholds[src];
    const float* seg = g_thr + f * SEG;
    unsigned pos = 0;                             // #{< thr}
    #pragma unroll
    for (int st = SEG / 2; st; st >>= 1)
        if (__ldg(seg + pos + st - 1) < thr) pos += st;
    g_nodes4[t * NSLOT + n] = ((unsigned)f << 24) | (pos + 1u);
}

// ---------------- 5: quantize x: qx = upper_bound(seg, v) ----------------
__global__ void quant_k() {
    __shared__ float s[SEG];
    int f = blockIdx.x;
    for (int i = threadIdx.x; i < SEG; i += 512) s[i] = g_thr[f * SEG + i];
    __syncthreads();
    const float* xr = g_xT + (size_t)f * BATCH;
    uint16_t* qr = g_qxT + (size_t)f * BATCH;
    for (int sidx = threadIdx.x; sidx < BATCH; sidx += 512) {
        float v = xr[sidx];
        unsigned pos = 0;                         // #{<= v}
        #pragma unroll
        for (int st = SEG / 2; st; st >>= 1)
            if (s[pos + st - 1] <= v) pos += st;
        qr[sidx] = (uint16_t)pos;
    }
}

// ---------------- helpers ----------------
__device__ __forceinline__ void bulk_fetch_nodes(unsigned dst, int g, unsigned mbar) {
    asm volatile("mbarrier.arrive.expect_tx.shared.b64 _, [%0], %1;"
                 :: "r"(mbar), "r"((unsigned)GRPBYTES) : "memory");
    const char* src = (const char*)g_nodes4 + (size_t)g * GRPBYTES;
    asm volatile("cp.async.bulk.shared::cta.global.mbarrier::complete_tx::bytes "
                 "[%0], [%1], %2, [%3];"
                 :: "r"(dst), "l"(src), "r"((unsigned)GRPBYTES), "r"(mbar) : "memory");
}

__device__ __forceinline__ void mbar_wait(unsigned mbar, unsigned parity) {
    unsigned done;
    asm volatile("{\n\t.reg .pred p;\n\t"
                 "mbarrier.try_wait.parity.acquire.cta.shared::cta.b64 p, [%1], %2;\n\t"
                 "selp.b32 %0, 1, 0, p;\n\t}"
                 : "=r"(done) : "r"(mbar), "r"(parity) : "memory");
    if (!done) {
        asm volatile("{\n\t.reg .pred P1;\n\t"
                     "W%=:\n\t"
                     "mbarrier.try_wait.parity.acquire.cta.shared::cta.b64 P1, [%0], %1, 0x989680;\n\t"
                     "@P1 bra.uni D%=;\n\t"
                     "bra.uni W%=;\n\t"
                     "D%=:\n\t}"
                     :: "r"(mbar), "r"(parity) : "memory");
    }
}

__device__ __forceinline__ void stage_x(char* sm, int s0, int tid) {
    uint4* xs4 = (uint4*)(sm + SM_X);                 // 4096 uint4 = 64KB
    #pragma unroll
    for (int j = 0; j < 8; j++) {
        int i4 = tid + THREADS * j;
        int f = i4 >> 4, o = i4 & 15;                 // 16 uint4 per 256B row
        xs4[i4] = *(const uint4*)((const char*)g_qxT + (size_t)f * (BATCH * 2) + s0 * 2 + o * 16);
    }
}

// ---------------- main traversal (persistent, quantized, double-buffered) ----------------
__global__ __launch_bounds__(THREADS, 1)
void traverse_k(const float* __restrict__ values, float* __restrict__ out) {
    extern __shared__ char sm[];
    int tid = threadIdx.x;

    unsigned smbase;
    asm("{ .reg .u64 t; cvta.to.shared.u64 t, %1; cvt.u32.u64 %0, t; }"
        : "=r"(smbase) : "l"(sm));

    int istart = (int)((long long)blockIdx.x * NITEMS / NSM);
    int iend   = (int)((long long)(blockIdx.x + 1) * NITEMS / NSM);

    int sl = tid & (SCHUNK - 1);
    int tl = tid >> 7;                           // 0..3
    unsigned xq = smbase + SM_X + sl * 2;        // u16 column base
    int tA = 2 * tl, tB = 2 * tl + 1;

    // prologue
    if (tid == 0) {
        asm volatile("mbarrier.init.shared.b64 [%0], 1;" :: "r"(smbase + SM_MBAR) : "memory");
        asm volatile("mbarrier.init.shared.b64 [%0], 1;" :: "r"(smbase + SM_MBAR + 8) : "memory");
    }
    __syncthreads();
    if (tid == 0) {
        bulk_fetch_nodes(smbase + SM_NODES, istart & (NGROUPS - 1), smbase + SM_MBAR);
        if (istart + 1 < iend)
            bulk_fetch_nodes(smbase + SM_NODES + GRPBYTES,
                             (istart + 1) & (NGROUPS - 1), smbase + SM_MBAR + 8);
    }
    int cur_chunk = istart >> 5;
    stage_x(sm, cur_chunk * SCHUNK, tid);
    __syncthreads();                              // x visible

    float4 vreg[4];
    float* prev_obase = out;

    for (int i = istart; i < iend; i++) {
        int k = i - istart;
        int buf = k & 1;
        int chunk = i >> 5;
        int g = i & (NGROUPS - 1);
        int s0 = chunk * SCHUNK;
        int t0 = g * GTREES;

        if (chunk != cur_chunk) {
            stage_x(sm, s0, tid);
            cur_chunk = chunk;
            __syncthreads();
        }

        // prev item's values gather (long-latency LDGs first)
        if (i > istart) {
            const unsigned* rb = (const unsigned*)(sm + SM_IDX + ((i - 1) & 1) * IDX_BYTES);
            #pragma unroll
            for (int j = 0; j < 4; j++) {
                int e = tid + THREADS * j;
                int sl2 = e >> 4, tg = (e >> 1) & 7, half = e & 1;
                unsigned vrow = rb[sl2 * IDX_PITCH + tg];
                vreg[j] = __ldg((const float4*)values + (size_t)vrow * 2 + half);
            }
        }

        mbar_wait(smbase + SM_MBAR + 8 * buf, (unsigned)((k >> 1) & 1));   // nodes[i] ready

        // ---- traversal: 2 interleaved chains, 4B node + 2B x loads
        unsigned baseA = smbase + SM_NODES + buf * GRPBYTES + tA * (NSLOT * 4);
        unsigned baseB = smbase + SM_NODES + buf * GRPBYTES + tB * (NSLOT * 4);
        unsigned cA = 4u - baseA, cB = 4u - baseB;
        unsigned oA = baseA, oB = baseB;
        #pragma unroll
        for (int d = 0; d < DEPTH; d++) {
            unsigned na, nb, qa, qb;
            asm("ld.shared.u32 %0, [%1];" : "=r"(na) : "r"(oA));
            asm("ld.shared.u32 %0, [%1];" : "=r"(nb) : "r"(oB));
            asm("ld.shared.u16 %0, [%1];" : "=r"(qa) : "r"(xq + (na >> 16)));
            asm("ld.shared.u16 %0, [%1];" : "=r"(qb) : "r"(xq + (nb >> 16)));
            oA = oA * 2u + cA + ((qa >= (na & 0xFFFFu)) ? 4u : 0u);
            oB = oB * 2u + cB + ((qb >= (nb & 0xFFFFu)) ? 4u : 0u);
        }
        unsigned leafA = (oA - baseA) >> 2;       // 1023..2046
        unsigned leafB = (oB - baseB) >> 2;

        // ---- store prev item's gathered values (coalesced)
        if (i > istart) {
            #pragma unroll
            for (int j = 0; j < 4; j++) {
                int e = tid + THREADS * j;
                int sl2 = e >> 4, tg = (e >> 1) & 7, half = e & 1;
                *(float4*)(prev_obase + (size_t)sl2 * (NTREE * NCLS) + tg * NCLS + half * 4) = vreg[j];
            }
        }

        // ---- publish values-row indices (pitch 9, conflict-free)
        {
            unsigned* wb = (unsigned*)(sm + SM_IDX + (i & 1) * IDX_BYTES);
            wb[sl * IDX_PITCH + tA] = (unsigned)(t0 + tA) * NNODE + leafA;
            wb[sl * IDX_PITCH + tB] = (unsigned)(t0 + tB) * NNODE + leafB;
        }
        __syncthreads();                          // idx visible; node reads of buf done

        if (i + 2 < iend && tid == 0)
            bulk_fetch_nodes(smbase + SM_NODES + buf * GRPBYTES,
                             (i + 2) & (NGROUPS - 1), smbase + SM_MBAR + 8 * buf);

        prev_obase = out + (size_t)s0 * (NTREE * NCLS) + t0 * NCLS;
    }

    // epilogue: gather + store for last item
    {
        const unsigned* rb = (const unsigned*)(sm + SM_IDX + ((iend - 1) & 1) * IDX_BYTES);
        #pragma unroll
        for (int j = 0; j < 4; j++) {
            int e = tid + THREADS * j;
            int sl2 = e >> 4, tg = (e >> 1) & 7, half = e & 1;
            unsigned vrow = rb[sl2 * IDX_PITCH + tg];
            vreg[j] = __ldg((const float4*)values + (size_t)vrow * 2 + half);
        }
        #pragma unroll
        for (int j = 0; j < 4; j++) {
            int e = tid + THREADS * j;
            int sl2 = e >> 4, tg = (e >> 1) & 7, half = e & 1;
            *(float4*)(prev_obase + (size_t)sl2 * (NTREE * NCLS) + tg * NCLS + half * 4) = vreg[j];
        }
    }
}

extern "C" void kernel_launch(void* const* d_in, const int* in_sizes, int n_in,
                              void* d_out, int out_size) {
    // metadata order: x, lefts, rights, features, thresholds, values, nodes_offset
    const float* x          = (const float*)d_in[0];
    const int*   features   = (const int*)  d_in[3];
    const float* thresholds = (const float*)d_in[4];
    const float* values     = (const float*)d_in[5];

    cudaFuncSetAttribute(traverse_k, cudaFuncAttributeMaxDynamicSharedMemorySize, SM_TOTAL);

    zero_k<<<(NFEAT * SEG + 1023) / 1024, 1024>>>();
    int prep_blocks = (NFEAT / 32) * (BATCH / 32) + (NTREE * 1023 + 255) / 256;
    prep1_k<<<prep_blocks, 256>>>(x, features, thresholds);
    sort_k<<<NFEAT, 512>>>();
    pack_k<<<(NTREE * 1023 + 255) / 256, 256>>>(features, thresholds);
    quant_k<<<NFEAT, 512>>>();
    traverse_k<<<NSM, THREADS, SM_TOTAL>>>(values, (float*)d_out);
}

// round 10
// speedup vs baseline: 1.9117x; 1.9117x over previous
#include <cuda_runtime.h>
#include <stdint.h>

#define BATCH   32768
#define NTREE   256
#define NNODE   2047
#define NFEAT   256
#define NCLS    8
#define DEPTH   10
#define SCHUNK  128
#define THREADS 512           // 2 squads x 256 (128 samples x 2 lanes x 2 chains)
#define GTREES  4
#define NCHUNK  (BATCH / SCHUNK)          // 256
#define NGROUPS (NTREE / GTREES)          // 64
#define NITEMS  (NCHUNK * NGROUPS)        // 16384, chunk-major
#define NSM     148
#define NSLOT   1024          // 8KB slab per tree (1023 internal nodes used)
#define GRPBYTES (GTREES * NSLOT * 8)     // 32768

// smem: [0,128K) x fp32 | [128K,+32K)x2 per-squad node bufs | 4x idx | mbars
#define SM_X      0
#define SM_NODES  131072
#define SM_IDX    196608
#define IDX_PITCH 5
#define IDX_BYTES (SCHUNK * IDX_PITCH * 4)   // 2560
#define SM_MBAR   (SM_IDX + 4 * IDX_BYTES)   // 206848
#define SM_TOTAL  (SM_MBAR + 16)

__device__ uint2 g_nodes2[NTREE * NSLOT];   // internal nodes: {thr bits, feat*512}
__device__ float g_xT[NFEAT * BATCH];       // x transposed [feature][sample]

// ---------------- merged prep: transpose x + pack nodes ----------------
__global__ void prep_k(const float* __restrict__ x,
                       const int* __restrict__ features,
                       const float* __restrict__ thresholds) {
    int b = blockIdx.x;
    const int TBLK = (NFEAT / 32) * (BATCH / 32);
    if (b < TBLK) {
        __shared__ float tile[32][33];
        int f0 = (b & 7) * 32, s0 = (b >> 3) * 32;
        int lx = threadIdx.x & 31, ly = threadIdx.x >> 5;   // 256 threads
        #pragma unroll
        for (int k = ly; k < 32; k += 8)
            tile[k][lx] = x[(size_t)(s0 + k) * NFEAT + f0 + lx];
        __syncthreads();
        #pragma unroll
        for (int k = ly; k < 32; k += 8)
            g_xT[(size_t)(f0 + k) * BATCH + s0 + lx] = tile[lx][k];
    } else {
        int i = (b - TBLK) * 256 + threadIdx.x;
        if (i < NTREE * 1023) {
            int t = i / 1023;
            int n = i - t * 1023;
            int src = t * NNODE + n;
            uint2 v;
            v.x = __float_as_uint(thresholds[src]);
            v.y = (unsigned)features[src] * (SCHUNK * 4);
            g_nodes2[t * NSLOT + n] = v;
        }
    }
}

// ---------------- helpers ----------------
__device__ __forceinline__ void stage_x(char* sm, int s0, int tid) {
    float4* xs4 = (float4*)(sm + SM_X);
    #pragma unroll
    for (int j = 0; j < 16; j++) {
        int i4 = tid + THREADS * j;                 // 8192 float4
        int f = i4 >> 5, o = i4 & 31;
        xs4[i4] = *(const float4*)(g_xT + (size_t)f * BATCH + s0 + o * 4);
    }
}

__device__ __forceinline__ void bulk_fetch_nodes(unsigned dst, int g, unsigned mbar) {
    asm volatile("mbarrier.arrive.expect_tx.shared.b64 _, [%0], %1;"
                 :: "r"(mbar), "r"((unsigned)GRPBYTES) : "memory");
    const char* src = (const char*)g_nodes2 + (size_t)g * GRPBYTES;
    asm volatile("cp.async.bulk.shared::cta.global.mbarrier::complete_tx::bytes "
                 "[%0], [%1], %2, [%3];"
                 :: "r"(dst), "l"(src), "r"((unsigned)GRPBYTES), "r"(mbar) : "memory");
}

__device__ __forceinline__ void mbar_wait(unsigned mbar, unsigned parity) {
    unsigned done;
    asm volatile("{\n\t.reg .pred p;\n\t"
                 "mbarrier.try_wait.parity.acquire.cta.shared::cta.b64 p, [%1], %2;\n\t"
                 "selp.b32 %0, 1, 0, p;\n\t}"
                 : "=r"(done) : "r"(mbar), "r"(parity) : "memory");
    if (!done) {
        asm volatile("{\n\t.reg .pred P1;\n\t"
                     "W%=:\n\t"
                     "mbarrier.try_wait.parity.acquire.cta.shared::cta.b64 P1, [%0], %1, 0x989680;\n\t"
                     "@P1 bra.uni D%=;\n\t"
                     "bra.uni W%=;\n\t"
                     "D%=:\n\t}"
                     :: "r"(mbar), "r"(parity) : "memory");
    }
}

// ---------------- main traversal (persistent, 2 independent squads) ----------------
__global__ __launch_bounds__(THREADS, 1)
void traverse_k(const float* __restrict__ values, float* __restrict__ out) {
    extern __shared__ char sm[];
    int tid = threadIdx.x;
    int squad = tid >> 8;                      // 0/1
    int tsq = tid & 255;

    unsigned smbase;
    asm("{ .reg .u64 t; cvta.to.shared.u64 t, %1; cvt.u32.u64 %0, t; }"
        : "=r"(smbase) : "l"(sm));

    int istart = (int)((long long)blockIdx.x * NITEMS / NSM);
    int iend   = (int)((long long)(blockIdx.x + 1) * NITEMS / NSM);

    int sl = tsq & (SCHUNK - 1);
    int tl = tsq >> 7;                         // 0..1 -> 2 chains each
    unsigned xaddr = smbase + SM_X + sl * 4;
    int tA = 2 * tl, tB = 2 * tl + 1;          // trees-in-group (0..3)
    unsigned nodebase = smbase + SM_NODES + squad * GRPBYTES;
    unsigned baseA = nodebase + tA * (NSLOT * 8);
    unsigned baseB = nodebase + tB * (NSLOT * 8);
    unsigned cA = 8u - baseA, cB = 8u - baseB;
    unsigned mbar = smbase + SM_MBAR + 8 * squad;
    unsigned idx0 = smbase + SM_IDX + squad * (2 * IDX_BYTES);
    int bar_id = 1 + squad;

    // prologue
    if (tid < 2)
        asm volatile("mbarrier.init.shared.b64 [%0], 1;"
                     :: "r"(smbase + SM_MBAR + 8 * tid) : "memory");
    __syncthreads();
    int i0 = istart + squad;
    if (tsq == 0 && i0 < iend)
        bulk_fetch_nodes(nodebase, i0 & (NGROUPS - 1), mbar);
    int base_chunk = istart >> 6;
    stage_x(sm, base_chunk * SCHUNK, tid);
    __syncthreads();                            // x visible to both squads

    float4 vreg[4];
    float* prev_obase = out;
    int c = 0;                                  // chunk-crossing events done
    int k = 0;                                  // squad item ordinal

    for (int i = i0; i < iend; i += 2, k++) {
        int chunk = i >> 6;
        if (chunk != base_chunk + c) {          // crossing event #c (paired across squads)
            __syncthreads();
            stage_x(sm, (base_chunk + c + 1) * SCHUNK, tid);
            c++;
            __syncthreads();
        }
        int g = i & (NGROUPS - 1);
        int t0 = g * GTREES;
        int s0 = chunk * SCHUNK;

        // prev item's values gather (long-latency LDGs before the wait)
        if (k > 0) {
            const unsigned* rb = (const unsigned*)(size_t)0;
            rb = (const unsigned*)(sm + SM_IDX + squad * (2 * IDX_BYTES) + ((k - 1) & 1) * IDX_BYTES);
            #pragma unroll
            for (int j = 0; j < 4; j++) {
                int e = tsq + 256 * j;          // 0..1023
                int sl2 = e >> 3, tg = (e >> 1) & 3, half = e & 1;
                unsigned vrow = rb[sl2 * IDX_PITCH + tg];
                vreg[j] = __ldg((const float4*)values + (size_t)vrow * 2 + half);
            }
        }

        mbar_wait(mbar, (unsigned)(k & 1));     // nodes[i] staged (acquire)

        // ---- traversal: 2 interleaved chains, all loads from shared
        unsigned oA = baseA, oB = baseB;
        #pragma unroll
        for (int d = 0; d < DEPTH; d++) {
            unsigned ax, ay, bx, by;
            asm("ld.shared.v2.u32 {%0,%1}, [%2];" : "=r"(ax), "=r"(ay) : "r"(oA));
            asm("ld.shared.v2.u32 {%0,%1}, [%2];" : "=r"(bx), "=r"(by) : "r"(oB));
            float fa, fb;
            asm("ld.shared.f32 %0, [%1];" : "=f"(fa) : "r"(xaddr + ay));
            asm("ld.shared.f32 %0, [%1];" : "=f"(fb) : "r"(xaddr + by));
            oA = oA * 2u + cA + ((fa >= __uint_as_float(ax)) ? 8u : 0u);
            oB = oB * 2u + cB + ((fb >= __uint_as_float(bx)) ? 8u : 0u);
        }
        unsigned leafA = (oA - baseA) >> 3;     // 1023..2046
        unsigned leafB = (oB - baseB) >> 3;

        // ---- store prev item's gathered values (coalesced)
        if (k > 0) {
            #pragma unroll
            for (int j = 0; j < 4; j++) {
                int e = tsq + 256 * j;
                int sl2 = e >> 3, tg = (e >> 1) & 3, half = e & 1;
                *(float4*)(prev_obase + (size_t)sl2 * (NTREE * NCLS) + tg * NCLS + half * 4) = vreg[j];
            }
        }

        // ---- publish this item's values-row indices (pitch 5, conflict-free)
        {
            unsigned* wb = (unsigned*)(sm + SM_IDX + squad * (2 * IDX_BYTES) + (k & 1) * IDX_BYTES);
            wb[sl * IDX_PITCH + tA] = (unsigned)(t0 + tA) * NNODE + leafA;
            wb[sl * IDX_PITCH + tB] = (unsigned)(t0 + tB) * NNODE + leafB;
        }
        asm volatile("bar.sync %0, %1;" :: "r"(bar_id), "r"(256) : "memory");  // squad-local

        // refill own node buffer for item i+2 (reads of it are done)
        if (i + 2 < iend && tsq == 0)
            bulk_fetch_nodes(nodebase, (i + 2) & (NGROUPS - 1), mbar);

        prev_obase = out + (size_t)s0 * (NTREE * NCLS) + t0 * NCLS;
    }

    // catch-up: match the other squad's remaining crossing events
    int K = ((iend - 1) >> 6) - base_chunk;
    while (c < K) {
        __syncthreads();
        stage_x(sm, (base_chunk + c + 1) * SCHUNK, tid);
        c++;
        __syncthreads();
    }

    // epilogue: gather + store for this squad's last item
    if (k > 0) {
        const unsigned* rb = (const unsigned*)(sm + SM_IDX + squad * (2 * IDX_BYTES) + ((k - 1) & 1) * IDX_BYTES);
        #pragma unroll
        for (int j = 0; j < 4; j++) {
            int e = tsq + 256 * j;
            int sl2 = e >> 3, tg = (e >> 1) & 3, half = e & 1;
            unsigned vrow = rb[sl2 * IDX_PITCH + tg];
            vreg[j] = __ldg((const float4*)values + (size_t)vrow * 2 + half);
        }
        #pragma unroll
        for (int j = 0; j < 4; j++) {
            int e = tsq + 256 * j;
            int sl2 = e >> 3, tg = (e >> 1) & 3, half = e & 1;
            *(float4*)(prev_obase + (size_t)sl2 * (NTREE * NCLS) + tg * NCLS + half * 4) = vreg[j];
        }
    }
}

extern "C" void kernel_launch(void* const* d_in, const int* in_sizes, int n_in,
                              void* d_out, int out_size) {
    // metadata order: x, lefts, rights, features, thresholds, values, nodes_offset
    const float* x          = (const float*)d_in[0];
    const int*   features   = (const int*)  d_in[3];
    const float* thresholds = (const float*)d_in[4];
    const float* values     = (const float*)d_in[5];

    cudaFuncSetAttribute(traverse_k, cudaFuncAttributeMaxDynamicSharedMemorySize, SM_TOTAL);

    int prep_blocks = (NFEAT / 32) * (BATCH / 32) + (NTREE * 1023 + 255) / 256;
    prep_k<<<prep_blocks, 256>>>(x, features, thresholds);
    traverse_k<<<NSM, THREADS, SM_TOTAL>>>(values, (float*)d_out);
}

// round 11
// speedup vs baseline: 1.9884x; 1.0401x over previous
#include <cuda_runtime.h>
#include <stdint.h>

#define BATCH   32768
#define NTREE   256
#define NNODE   2047
#define NFEAT   256
#define NCLS    8
#define DEPTH   10
#define SCHUNK  128
#define THREADS 512           // 128 samples x 4 tree-lanes (2 chains each)
#define GTREES  8
#define NCHUNK  (BATCH / SCHUNK)          // 256
#define NGROUPS (NTREE / GTREES)          // 32
#define NITEMS  (NCHUNK * NGROUPS)        // 8192, chunk-major
#define NSLOT   1024          // 8KB slab per tree (1023 internal nodes used)
#define GRPBYTES (GTREES * NSLOT * 8)     // 65536

// smem map: [0,128K) x-tile | [128K,192K) node buffer | [192K,+9K) idx x2 | mbar
#define SM_X      0
#define SM_NODES  131072
#define SM_IDX    196608
#define IDX_PITCH 9
#define IDX_BYTES (SCHUNK * IDX_PITCH * 4)   // 4608
#define SM_MBAR   (196608 + 2 * IDX_BYTES)
#define SM_TOTAL  (SM_MBAR + 16)

__device__ uint2 g_nodes2[NTREE * NSLOT];   // internal nodes: {thr bits, feat*512}
__device__ float g_xT[NFEAT * BATCH];       // x transposed [feature][sample]

// ---------------- merged prep: transpose x + pack nodes ----------------
__global__ void prep_k(const float* __restrict__ x,
                       const int* __restrict__ features,
                       const float* __restrict__ thresholds) {
    int b = blockIdx.x;
    const int TBLK = (NFEAT / 32) * (BATCH / 32);
    if (b < TBLK) {
        __shared__ float tile[32][33];
        int f0 = (b & 7) * 32, s0 = (b >> 3) * 32;
        int lx = threadIdx.x & 31, ly = threadIdx.x >> 5;   // 256 threads
        #pragma unroll
        for (int k = ly; k < 32; k += 8)
            tile[k][lx] = x[(size_t)(s0 + k) * NFEAT + f0 + lx];
        __syncthreads();
        #pragma unroll
        for (int k = ly; k < 32; k += 8)
            g_xT[(size_t)(f0 + k) * BATCH + s0 + lx] = tile[lx][k];
    } else {
        int i = (b - TBLK) * 256 + threadIdx.x;
        if (i < NTREE * 1023) {
            int t = i / 1023;
            int n = i - t * 1023;
            int src = t * NNODE + n;
            uint2 v;
            v.x = __float_as_uint(thresholds[src]);
            v.y = (unsigned)features[src] * (SCHUNK * 4);
            g_nodes2[t * NSLOT + n] = v;
        }
    }
}

// ---------------- helpers ----------------
__device__ __forceinline__ void stage_x(char* sm, int s0, int tid) {
    float4* xs4 = (float4*)(sm + SM_X);
    #pragma unroll
    for (int j = 0; j < 16; j++) {
        int i4 = tid + THREADS * j;                 // 8192 float4
        int f = i4 >> 5, o = i4 & 31;
        xs4[i4] = *(const float4*)(g_xT + (size_t)f * BATCH + s0 + o * 4);
    }
}

__device__ __forceinline__ void bulk_fetch_nodes(unsigned dst, int g, unsigned mbar) {
    // one-shot 64KB DMA: expect_tx + bulk copy (caller: single thread)
    asm volatile("mbarrier.arrive.expect_tx.shared.b64 _, [%0], %1;"
                 :: "r"(mbar), "r"((unsigned)GRPBYTES) : "memory");
    const char* src = (const char*)g_nodes2 + (size_t)g * GRPBYTES;
    asm volatile("cp.async.bulk.shared::cta.global.mbarrier::complete_tx::bytes "
                 "[%0], [%1], %2, [%3];"
                 :: "r"(dst), "l"(src), "r"((unsigned)GRPBYTES), "r"(mbar) : "memory");
}

__device__ __forceinline__ void mbar_wait(unsigned mbar, unsigned parity) {
    unsigned done;
    asm volatile("{\n\t.reg .pred p;\n\t"
                 "mbarrier.try_wait.parity.acquire.cta.shared::cta.b64 p, [%1], %2;\n\t"
                 "selp.b32 %0, 1, 0, p;\n\t}"
                 : "=r"(done) : "r"(mbar), "r"(parity) : "memory");
    if (!done) {
        asm volatile("{\n\t.reg .pred P1;\n\t"
                     "W%=:\n\t"
                     "mbarrier.try_wait.parity.acquire.cta.shared::cta.b64 P1, [%0], %1, 0x989680;\n\t"
                     "@P1 bra.uni D%=;\n\t"
                     "bra.uni W%=;\n\t"
                     "D%=:\n\t}"
                     :: "r"(mbar), "r"(parity) : "memory");
    }
}

// ---------------- main traversal (persistent) ----------------
__global__ __launch_bounds__(THREADS, 1)
void traverse_k(const float* __restrict__ values, float* __restrict__ out, int nsm) {
    extern __shared__ char sm[];
    int tid = threadIdx.x;

    unsigned smbase;
    asm("{ .reg .u64 t; cvta.to.shared.u64 t, %1; cvt.u32.u64 %0, t; }"
        : "=r"(smbase) : "l"(sm));
    unsigned mbar = smbase + SM_MBAR;

    int istart = (int)((long long)blockIdx.x * NITEMS / nsm);
    int iend   = (int)((long long)(blockIdx.x + 1) * NITEMS / nsm);

    int sl = tid & (SCHUNK - 1);
    int tl = tid >> 7;                         // 0..3
    unsigned xaddr = smbase + SM_X + sl * 4;
    int tA = 2 * tl, tB = 2 * tl + 1;
    unsigned baseA = smbase + SM_NODES + tA * (NSLOT * 8);
    unsigned baseB = smbase + SM_NODES + tB * (NSLOT * 8);
    unsigned cA = 8u - baseA, cB = 8u - baseB;

    // prologue
    if (tid == 0)
        asm volatile("mbarrier.init.shared.b64 [%0], 1;" :: "r"(mbar) : "memory");
    __syncthreads();
    if (tid == 0) bulk_fetch_nodes(smbase + SM_NODES, istart & (NGROUPS - 1), mbar);
    int cur_chunk = istart >> 5;
    stage_x(sm, cur_chunk * SCHUNK, tid);
    __syncthreads();                            // x visible

    float4 vreg[4];
    float* prev_obase = out;

    for (int i = istart; i < iend; i++) {
        int k = i - istart;
        int chunk = i >> 5;
        int g = i & (NGROUPS - 1);
        int s0 = chunk * SCHUNK;
        int t0 = g * GTREES;

        if (chunk != cur_chunk) {               // all threads past prev barrier
            stage_x(sm, s0, tid);
            cur_chunk = chunk;
            __syncthreads();                    // x visible before traversal
        }

        // issue prev item's values gather (long-latency LDGs before the wait)
        if (i > istart) {
            const unsigned* rb = (const unsigned*)(sm + SM_IDX + ((i - 1) & 1) * IDX_BYTES);
            #pragma unroll
            for (int j = 0; j < 4; j++) {
                int e = tid + THREADS * j;
                int sl2 = e >> 4, tg = (e >> 1) & 7, half = e & 1;
                unsigned vrow = rb[sl2 * IDX_PITCH + tg];
                vreg[j] = __ldg((const float4*)values + (size_t)vrow * 2 + half);
            }
        }

        mbar_wait(mbar, (unsigned)(k & 1));     // nodes[i] staged (acquire)

        // ---- traversal: 2 interleaved chains, all loads from shared
        unsigned oA = baseA, oB = baseB;
        #pragma unroll
        for (int d = 0; d < DEPTH; d++) {
            unsigned ax, ay, bx, by;
            asm("ld.shared.v2.u32 {%0,%1}, [%2];" : "=r"(ax), "=r"(ay) : "r"(oA));
            asm("ld.shared.v2.u32 {%0,%1}, [%2];" : "=r"(bx), "=r"(by) : "r"(oB));
            float fa, fb;
            asm("ld.shared.f32 %0, [%1];" : "=f"(fa) : "r"(xaddr + ay));
            asm("ld.shared.f32 %0, [%1];" : "=f"(fb) : "r"(xaddr + by));
            oA = oA * 2u + cA + ((fa >= __uint_as_float(ax)) ? 8u : 0u);
            oB = oB * 2u + cB + ((fb >= __uint_as_float(bx)) ? 8u : 0u);
        }
        unsigned leafA = (oA - baseA) >> 3;     // 1023..2046
        unsigned leafB = (oB - baseB) >> 3;

        // ---- store prev item's gathered values (coalesced)
        if (i > istart) {
            #pragma unroll
            for (int j = 0; j < 4; j++) {
                int e = tid + THREADS * j;
                int sl2 = e >> 4, tg = (e >> 1) & 7, half = e & 1;
                *(float4*)(prev_obase + (size_t)sl2 * (NTREE * NCLS) + tg * NCLS + half * 4) = vreg[j];
            }
        }

        // ---- publish this item's values-row indices (pitch 9, conflict-free)
        {
            unsigned* wb = (unsigned*)(sm + SM_IDX + (i & 1) * IDX_BYTES);
            wb[sl * IDX_PITCH + tA] = (unsigned)(t0 + tA) * NNODE + leafA;
            wb[sl * IDX_PITCH + tB] = (unsigned)(t0 + tB) * NNODE + leafB;
        }
        __syncthreads();                        // idx visible; node reads done

        if (i + 1 < iend && tid == 0)
            bulk_fetch_nodes(smbase + SM_NODES, (i + 1) & (NGROUPS - 1), mbar);

        prev_obase = out + (size_t)s0 * (NTREE * NCLS) + t0 * NCLS;
    }

    // epilogue: gather + store for the last item
    {
        const unsigned* rb = (const unsigned*)(sm + SM_IDX + ((iend - 1) & 1) * IDX_BYTES);
        #pragma unroll
        for (int j = 0; j < 4; j++) {
            int e = tid + THREADS * j;
            int sl2 = e >> 4, tg = (e >> 1) & 7, half = e & 1;
            unsigned vrow = rb[sl2 * IDX_PITCH + tg];
            vreg[j] = __ldg((const float4*)values + (size_t)vrow * 2 + half);
        }
        #pragma unroll
        for (int j = 0; j < 4; j++) {
            int e = tid + THREADS * j;
            int sl2 = e >> 4, tg = (e >> 1) & 7, half = e & 1;
            *(float4*)(prev_obase + (size_t)sl2 * (NTREE * NCLS) + tg * NCLS + half * 4) = vreg[j];
        }
    }
}

extern "C" void kernel_launch(void* const* d_in, const int* in_sizes, int n_in,
                              void* d_out, int out_size) {
    // metadata order: x, lefts, rights, features, thresholds, values, nodes_offset
    const float* x          = (const float*)d_in[0];
    const int*   features   = (const int*)  d_in[3];
    const float* thresholds = (const float*)d_in[4];
    const float* values     = (const float*)d_in[5];

    static int nsm = 0;                        // deterministic per-device constant
    if (nsm == 0) {
        int dev = 0;
        cudaGetDevice(&dev);
        cudaDeviceGetAttribute(&nsm, cudaDevAttrMultiProcessorCount, dev);
        if (nsm <= 0) nsm = 148;
    }

    cudaFuncSetAttribute(traverse_k, cudaFuncAttributeMaxDynamicSharedMemorySize, SM_TOTAL);

    int prep_blocks = (NFEAT / 32) * (BATCH / 32) + (NTREE * 1023 + 255) / 256;
    prep_k<<<prep_blocks, 256>>>(x, features, thresholds);
    traverse_k<<<nsm, THREADS, SM_TOTAL>>>(values, (float*)d_out, nsm);
}